// round 15
// baseline (speedup 1.0000x reference)
#include <cuda_runtime.h>
#include <cuda_fp16.h>

// Problem constants
#define BB   4
#define CC   3
#define HH   1024
#define WW   1024
#define SW   (WW + 4)           // acc row stride in pixels: 2 guard cols each side
#define HWN  (HH * WW)          // 1<<20
#define NPIX (BB * HWN)         // 1<<22
#define NELEM (BB * CC * HWN)   // 12,582,912
#define NPAIR (NPIX / 2)

// Single fp16 accumulator per f: channel-last padded [B,H,SW,4] (8B/pixel).
// 33.7 MB per f, 67.4 MB total -> fits the 126 MB L2.
// Zero-initialized at module load. The loss pass RESETS every element it
// reads using write-back stores, so the zeroed lines stay L2-resident and
// every subsequent graph replay starts from a clean, warm accumulator.
// Guard columns are write-only (never read, never reset; accumulate only
// non-negative values).
#define ACC_HALVES ((size_t)BB * HH * SW * 4)
__device__ __align__(16) __half g_acc[2][ACC_HALVES];

#define TPB        256
#define SPLAT_BLKS (NPIX / TPB)   // 16384 per f
#define LBLK       1184           // loss-role blocks

static __device__ __forceinline__ unsigned pack2(float a, float b) {
    __half2 h = __floats2half2_rn(a, b);
    return *reinterpret_cast<unsigned*>(&h);
}
static __device__ __forceinline__ void red_v4h(__half* p, unsigned a, unsigned b,
                                               unsigned c, unsigned d) {
    asm volatile("red.global.add.noftz.v4.f16x2 [%0], {%1, %2, %3, %4};"
                 :: "l"(p), "r"(a), "r"(b), "r"(c), "r"(d) : "memory");
}
static __device__ __forceinline__ void red_v2h(__half* p, unsigned a, unsigned b) {
    asm volatile("red.global.add.noftz.v2.f16x2 [%0], {%1, %2};"
                 :: "l"(p), "r"(a), "r"(b) : "memory");
}

// ---------- role bodies ----------

// Splat one source pixel of warp f. r in [0, NPIX).
static __device__ __forceinline__ void splat_dev(const float* __restrict__ flows,
                                                 const float* __restrict__ im0,
                                                 const float* __restrict__ im1,
                                                 const float* __restrict__ tval,
                                                 int f, unsigned r) {
    const int      b = r >> 20;
    const unsigned p = r & (HWN - 1);
    const int      h = p >> 10;
    const int      w = p & (WW - 1);

    const float t = tval[b];
    const float s = f ? (1.0f / (1.0f - t)) : (1.0f / t);

    const float* fb = flows + ((size_t)(f * BB + b) * 2) * HWN;
    const float X = (float)w + s * __ldcs(&fb[p]);
    const float Y = (float)h + s * __ldcs(&fb[HWN + p]);

    const float x0f = floorf(X), y0f = floorf(Y);
    const int   x0 = (int)x0f,  y0 = (int)y0f;
    const float fx = X - x0f,   fy = Y - y0f;

    if (x0 < -1 || x0 > WW - 1) return;
    if (y0 < -1 || y0 > HH - 1) return;

    const float* im = f ? im1 : im0;
    const float v0 = __ldcs(&im[((size_t)b * CC + 0) * HWN + p]);
    const float v1 = __ldcs(&im[((size_t)b * CC + 1) * HWN + p]);
    const float v2 = __ldcs(&im[((size_t)b * CC + 2) * HWN + p]);

    __half* buf = g_acc[f];
    const bool even = (x0 & 1) == 0;

    #pragma unroll
    for (int rr = 0; rr < 2; rr++) {
        const int y = y0 + rr;
        if ((unsigned)y >= (unsigned)HH) continue;
        const float wy = rr ? fy : (1.0f - fy);
        const float wa = (1.0f - fx) * wy;    // corner x0
        const float wb = fx * wy;             // corner x0+1
        __half* dst = buf + ((size_t)(b * HH + y) * SW + 2 + x0) * 4;
        const unsigned a0 = pack2(wa * v0, wa * v1);
        const unsigned a1 = pack2(wa * v2, 0.0f);
        const unsigned b0 = pack2(wb * v0, wb * v1);
        const unsigned b1 = pack2(wb * v2, 0.0f);
        if (even) {
            red_v4h(dst, a0, a1, b0, b1);
        } else {
            red_v2h(dst, a0, a1);
            red_v2h(dst + 4, b0, b1);
        }
    }
}

// Partial loss for one f: 2 px/thread. Reads the accumulator pair (16B, plain
// load) and RESETS it with a write-back store (line stays L2-resident for the
// next replay's splat). Block-reduce, one atomicAdd per block.
static __device__ __forceinline__ void loss_dev(const float* __restrict__ ref,
                                                int f, unsigned rb, unsigned nblk,
                                                float* __restrict__ out) {
    float acc = 0.f;
    const unsigned stride = nblk * TPB;
    const uint4 zero4 = make_uint4(0u, 0u, 0u, 0u);
    for (unsigned i = rb * TPB + threadIdx.x; i < NPAIR; i += stride) {
        const unsigned pp = i << 1;
        const int      b  = pp >> 20;
        const unsigned p  = pp & (HWN - 1);
        const int      y  = p >> 10;
        const int      x  = p & (WW - 1);          // even
        const size_t ai = (((size_t)(b * HH + y)) * SW + 2 + x) * 4;  // 16B aligned

        uint4* ap = reinterpret_cast<uint4*>(&g_acc[f][ai]);
        const uint4 u = *ap;                       // plain load (keep residency)
        *ap = zero4;                               // write-back reset (stays in L2)
        const float2 p0a = __half22float2(*reinterpret_cast<const __half2*>(&u.x));
        const float2 p0b = __half22float2(*reinterpret_cast<const __half2*>(&u.y));
        const float2 p1a = __half22float2(*reinterpret_cast<const __half2*>(&u.z));
        const float2 p1b = __half22float2(*reinterpret_cast<const __half2*>(&u.w));

        const size_t base = (size_t)b * CC * HWN + p;
        const float2 r0 = __ldcs(reinterpret_cast<const float2*>(&ref[base]));
        const float2 r1 = __ldcs(reinterpret_cast<const float2*>(&ref[base + HWN]));
        const float2 r2 = __ldcs(reinterpret_cast<const float2*>(&ref[base + 2 * HWN]));

        acc += fabsf(p0a.x - r0.x) + fabsf(p0a.y - r1.x) + fabsf(p0b.x - r2.x);
        acc += fabsf(p1a.x - r0.y) + fabsf(p1a.y - r1.y) + fabsf(p1b.x - r2.y);
    }
    #pragma unroll
    for (int o = 16; o; o >>= 1) acc += __shfl_down_sync(0xffffffffu, acc, o);
    __shared__ float sb[8];
    const int lane = threadIdx.x & 31, wid = threadIdx.x >> 5;
    if (lane == 0) sb[wid] = acc;
    __syncthreads();
    if (wid == 0) {
        acc = (lane < (TPB >> 5)) ? sb[lane] : 0.f;
        #pragma unroll
        for (int o = 16; o; o >>= 1) acc += __shfl_down_sync(0xffffffffu, acc, o);
        if (lane == 0) atomicAdd(out, acc * (1.0f / (float)NELEM));
    }
}

// ---------- kernels ----------

// k2: splat f0. Block 0 thread 0 resets out (no loss atomics until k3).
__global__ void __launch_bounds__(TPB) k2_splat0(
        const float* __restrict__ flows, const float* __restrict__ im0,
        const float* __restrict__ im1, const float* __restrict__ tval,
        float* __restrict__ out) {
    if (blockIdx.x == 0 && threadIdx.x == 0) *out = 0.f;
    const unsigned r = blockIdx.x * TPB + threadIdx.x;
    splat_dev(flows, im0, im1, tval, 0, r);
}

// k3: loss f0 (+reset acc0) in blocks [0,LBLK); splat f1 in the rest.
__global__ void __launch_bounds__(TPB) k3_loss0_splat1(
        const float* __restrict__ flows, const float* __restrict__ im0,
        const float* __restrict__ im1, const float* __restrict__ tval,
        float* __restrict__ out) {
    if (blockIdx.x < LBLK) {
        loss_dev(im1, 0, blockIdx.x, LBLK, out);   // warp0 vs im1
    } else {
        const unsigned r = (blockIdx.x - LBLK) * TPB + threadIdx.x;
        splat_dev(flows, im0, im1, tval, 1, r);
    }
}

// k4: loss f1 (+reset acc1)
__global__ void __launch_bounds__(TPB) k4_loss1(const float* __restrict__ im0,
                                                float* __restrict__ out) {
    loss_dev(im0, 1, blockIdx.x, gridDim.x, out);  // warp1 vs im0
}

extern "C" void kernel_launch(void* const* d_in, const int* in_sizes, int n_in,
                              void* d_out, int out_size) {
    const float* flows = (const float*)d_in[0];   // [2,B,2,H,W]
    const float* im0   = (const float*)d_in[1];   // [B,C,H,W]
    const float* im1   = (const float*)d_in[2];   // [B,C,H,W]
    const float* tval  = (const float*)d_in[3];   // [B]
    float* out = (float*)d_out;

    k2_splat0<<<SPLAT_BLKS, TPB>>>(flows, im0, im1, tval, out);
    k3_loss0_splat1<<<LBLK + SPLAT_BLKS, TPB>>>(flows, im0, im1, tval, out);
    k4_loss1<<<LBLK, TPB>>>(im0, out);
}

// round 16
// speedup vs baseline: 1.5322x; 1.5322x over previous
#include <cuda_runtime.h>
#include <cuda_fp16.h>

// Problem constants
#define BB   4
#define CC   3
#define HH   1024
#define WW   1024
#define SW   (WW + 4)           // acc row stride in pixels: 2 guard cols each side
#define HWN  (HH * WW)          // 1<<20
#define NPIX (BB * HWN)         // 1<<22
#define NELEM (BB * CC * HWN)   // 12,582,912
#define NPAIR (NPIX / 2)

// Single fp16 accumulator per f: channel-last padded [B,H,SW,4] (8B/pixel).
// 33.7 MB per f, 67.4 MB total -> fits the 126 MB L2.
#define ACC_HALVES ((size_t)BB * HH * SW * 4)
__device__ __align__(16) __half g_acc[2][ACC_HALVES];

#define TPB        256
#define SPLAT_BLKS (NPIX / TPB)   // 16384 per f
#define ZBLK       1184           // zero-role blocks (148*8)
#define LBLK       1184           // loss-role blocks (148*8)

static __device__ __forceinline__ unsigned pack2(float a, float b) {
    __half2 h = __floats2half2_rn(a, b);
    return *reinterpret_cast<unsigned*>(&h);
}
static __device__ __forceinline__ void red_v4h(__half* p, unsigned a, unsigned b,
                                               unsigned c, unsigned d) {
    asm volatile("red.global.add.noftz.v4.f16x2 [%0], {%1, %2, %3, %4};"
                 :: "l"(p), "r"(a), "r"(b), "r"(c), "r"(d) : "memory");
}
static __device__ __forceinline__ void red_v2h(__half* p, unsigned a, unsigned b) {
    asm volatile("red.global.add.noftz.v2.f16x2 [%0], {%1, %2};"
                 :: "l"(p), "r"(a), "r"(b) : "memory");
}

// ---------- role bodies ----------

// Zero accumulator of one f (grid-stride float4 streaming stores).
static __device__ __forceinline__ void zero_f_dev(int f, unsigned rb, unsigned nblk) {
    const unsigned tidg = rb * TPB + threadIdx.x;
    const unsigned stride = nblk * TPB;
    float4* a = reinterpret_cast<float4*>(&g_acc[f][0]);
    const float4 z = make_float4(0.f, 0.f, 0.f, 0.f);
    const size_t n4 = ACC_HALVES / 8;
    for (size_t i = tidg; i < n4; i += stride) __stcs(&a[i], z);
}

// Splat one source pixel of warp f. r in [0, NPIX).
static __device__ __forceinline__ void splat_dev(const float* __restrict__ flows,
                                                 const float* __restrict__ im0,
                                                 const float* __restrict__ im1,
                                                 const float* __restrict__ tval,
                                                 int f, unsigned r) {
    const int      b = r >> 20;
    const unsigned p = r & (HWN - 1);
    const int      h = p >> 10;
    const int      w = p & (WW - 1);

    const float t = tval[b];
    const float s = f ? (1.0f / (1.0f - t)) : (1.0f / t);

    const float* fb = flows + ((size_t)(f * BB + b) * 2) * HWN;
    const float X = (float)w + s * __ldcs(&fb[p]);
    const float Y = (float)h + s * __ldcs(&fb[HWN + p]);

    const float x0f = floorf(X), y0f = floorf(Y);
    const int   x0 = (int)x0f,  y0 = (int)y0f;
    const float fx = X - x0f,   fy = Y - y0f;

    if (x0 < -1 || x0 > WW - 1) return;
    if (y0 < -1 || y0 > HH - 1) return;

    const float* im = f ? im1 : im0;
    const float v0 = __ldcs(&im[((size_t)b * CC + 0) * HWN + p]);
    const float v1 = __ldcs(&im[((size_t)b * CC + 1) * HWN + p]);
    const float v2 = __ldcs(&im[((size_t)b * CC + 2) * HWN + p]);

    __half* buf = g_acc[f];
    const bool even = (x0 & 1) == 0;

    #pragma unroll
    for (int rr = 0; rr < 2; rr++) {
        const int y = y0 + rr;
        if ((unsigned)y >= (unsigned)HH) continue;
        const float wy = rr ? fy : (1.0f - fy);
        const float wa = (1.0f - fx) * wy;    // corner x0
        const float wb = fx * wy;             // corner x0+1
        __half* dst = buf + ((size_t)(b * HH + y) * SW + 2 + x0) * 4;
        const unsigned a0 = pack2(wa * v0, wa * v1);
        const unsigned a1 = pack2(wa * v2, 0.0f);
        const unsigned b0 = pack2(wb * v0, wb * v1);
        const unsigned b1 = pack2(wb * v2, 0.0f);
        if (even) {
            red_v4h(dst, a0, a1, b0, b1);
        } else {
            red_v2h(dst, a0, a1);
            red_v2h(dst + 4, b0, b1);
        }
    }
}

// Partial loss for one f: sum |warp_f - ref| (2 px/thread), block-reduce,
// one atomicAdd per block.
static __device__ __forceinline__ void loss_dev(const float* __restrict__ ref,
                                                int f, unsigned rb, unsigned nblk,
                                                float* __restrict__ out) {
    float acc = 0.f;
    const unsigned stride = nblk * TPB;
    for (unsigned i = rb * TPB + threadIdx.x; i < NPAIR; i += stride) {
        const unsigned pp = i << 1;
        const int      b  = pp >> 20;
        const unsigned p  = pp & (HWN - 1);
        const int      y  = p >> 10;
        const int      x  = p & (WW - 1);          // even
        const size_t ai = (((size_t)(b * HH + y)) * SW + 2 + x) * 4;  // 16B aligned

        const uint4 u = __ldcs(reinterpret_cast<const uint4*>(&g_acc[f][ai]));
        const float2 p0a = __half22float2(*reinterpret_cast<const __half2*>(&u.x));
        const float2 p0b = __half22float2(*reinterpret_cast<const __half2*>(&u.y));
        const float2 p1a = __half22float2(*reinterpret_cast<const __half2*>(&u.z));
        const float2 p1b = __half22float2(*reinterpret_cast<const __half2*>(&u.w));

        const size_t base = (size_t)b * CC * HWN + p;
        const float2 r0 = __ldcs(reinterpret_cast<const float2*>(&ref[base]));
        const float2 r1 = __ldcs(reinterpret_cast<const float2*>(&ref[base + HWN]));
        const float2 r2 = __ldcs(reinterpret_cast<const float2*>(&ref[base + 2 * HWN]));

        acc += fabsf(p0a.x - r0.x) + fabsf(p0a.y - r1.x) + fabsf(p0b.x - r2.x);
        acc += fabsf(p1a.x - r0.y) + fabsf(p1a.y - r1.y) + fabsf(p1b.x - r2.y);
    }
    #pragma unroll
    for (int o = 16; o; o >>= 1) acc += __shfl_down_sync(0xffffffffu, acc, o);
    __shared__ float sb[8];
    const int lane = threadIdx.x & 31, wid = threadIdx.x >> 5;
    if (lane == 0) sb[wid] = acc;
    __syncthreads();
    if (wid == 0) {
        acc = (lane < (TPB >> 5)) ? sb[lane] : 0.f;
        #pragma unroll
        for (int o = 16; o; o >>= 1) acc += __shfl_down_sync(0xffffffffu, acc, o);
        if (lane == 0) atomicAdd(out, acc * (1.0f / (float)NELEM));
    }
}

// ---------- kernels ----------

__global__ void __launch_bounds__(TPB) k1_zero0(float* __restrict__ out) {
    zero_f_dev(0, blockIdx.x, gridDim.x);
    if (blockIdx.x == 0 && threadIdx.x == 0) *out = 0.f;
}

__global__ void __launch_bounds__(TPB) k2_zero1_splat0(
        const float* __restrict__ flows, const float* __restrict__ im0,
        const float* __restrict__ im1, const float* __restrict__ tval) {
    if (blockIdx.x < ZBLK) {
        zero_f_dev(1, blockIdx.x, ZBLK);
    } else {
        const unsigned r = (blockIdx.x - ZBLK) * TPB + threadIdx.x;
        splat_dev(flows, im0, im1, tval, 0, r);
    }
}

__global__ void __launch_bounds__(TPB) k3_loss0_splat1(
        const float* __restrict__ flows, const float* __restrict__ im0,
        const float* __restrict__ im1, const float* __restrict__ tval,
        float* __restrict__ out) {
    if (blockIdx.x < LBLK) {
        loss_dev(im1, 0, blockIdx.x, LBLK, out);   // warp0 vs im1
    } else {
        const unsigned r = (blockIdx.x - LBLK) * TPB + threadIdx.x;
        splat_dev(flows, im0, im1, tval, 1, r);
    }
}

__global__ void __launch_bounds__(TPB) k4_loss1(const float* __restrict__ im0,
                                                float* __restrict__ out) {
    loss_dev(im0, 1, blockIdx.x, gridDim.x, out);  // warp1 vs im0
}

extern "C" void kernel_launch(void* const* d_in, const int* in_sizes, int n_in,
                              void* d_out, int out_size) {
    const float* flows = (const float*)d_in[0];   // [2,B,2,H,W]
    const float* im0   = (const float*)d_in[1];   // [B,C,H,W]
    const float* im1   = (const float*)d_in[2];   // [B,C,H,W]
    const float* tval  = (const float*)d_in[3];   // [B]
    float* out = (float*)d_out;

    k1_zero0<<<ZBLK, TPB>>>(out);
    k2_zero1_splat0<<<ZBLK + SPLAT_BLKS, TPB>>>(flows, im0, im1, tval);
    k3_loss0_splat1<<<LBLK + SPLAT_BLKS, TPB>>>(flows, im0, im1, tval, out);
    k4_loss1<<<LBLK, TPB>>>(im0, out);
}